// round 14
// baseline (speedup 1.0000x reference)
#include <cuda_runtime.h>
#include <cuda_fp16.h>
#include <math.h>
#include <stdint.h>

#define S_LEN 2048
#define HID   4096
#define NH    32
#define NKV   8
#define HD    128
#define KV_DIM 1024
#define QKV_W 6144
#define QK_EPS 1e-6f

// ---------------- scratch ----------------
__device__ __half g_hsh[S_LEN * HID];
__device__ __half g_Wqkv16[QKV_W * HID];
__device__ __half g_Wo16[HID * HID];
__device__ __half g_QKV[S_LEN * QKV_W];
__device__ __half g_Qh[S_LEN * HID];
__device__ __half g_Kh[S_LEN * KV_DIM];
__device__ __half g_aoh[S_LEN * HID];

// =====================================================================
// portable PTX helpers
// =====================================================================
__device__ __forceinline__ uint32_t smem_to_u32(const void* smem_ptr) {
    uint32_t addr;
    asm("{ .reg .u64 tmp; cvta.to.shared.u64 tmp, %1; cvt.u32.u64 %0, tmp; }"
        : "=r"(addr) : "l"(smem_ptr));
    return addr;
}

__device__ __forceinline__ void cp_async16(uint32_t dst, const void* src) {
    asm volatile("cp.async.cg.shared.global [%0], [%1], 16;"
                 :: "r"(dst), "l"(src));
}
#define CP_COMMIT() asm volatile("cp.async.commit_group;" ::: "memory")
#define CP_WAIT(n)  asm volatile("cp.async.wait_group %0;" :: "n"(n) : "memory")

__device__ __forceinline__ void ldsm_x4(uint32_t (&r)[4], uint32_t addr) {
    asm volatile("ldmatrix.sync.aligned.m8n8.x4.shared.b16 {%0,%1,%2,%3}, [%4];"
        : "=r"(r[0]), "=r"(r[1]), "=r"(r[2]), "=r"(r[3]) : "r"(addr));
}

__device__ __forceinline__ void ldsm_x4_trans(uint32_t (&r)[4], uint32_t addr) {
    asm volatile("ldmatrix.sync.aligned.m8n8.x4.trans.shared.b16 {%0,%1,%2,%3}, [%4];"
        : "=r"(r[0]), "=r"(r[1]), "=r"(r[2]), "=r"(r[3]) : "r"(addr));
}

// fp32 accumulate (GEMMs, PV)
__device__ __forceinline__ void mma16816h(float (&d)[4], const uint32_t (&a)[4],
                                          uint32_t b0, uint32_t b1) {
    asm volatile(
        "mma.sync.aligned.m16n8k16.row.col.f32.f16.f16.f32 "
        "{%0,%1,%2,%3}, {%4,%5,%6,%7}, {%8,%9}, {%0,%1,%2,%3};"
        : "+f"(d[0]), "+f"(d[1]), "+f"(d[2]), "+f"(d[3])
        : "r"(a[0]), "r"(a[1]), "r"(a[2]), "r"(a[3]), "r"(b0), "r"(b1));
}

// fp16 accumulate (flash QK — scores bounded by qk-norm)
__device__ __forceinline__ void mma16816hh(uint32_t (&d)[2], const uint32_t (&a)[4],
                                           uint32_t b0, uint32_t b1) {
    asm volatile(
        "mma.sync.aligned.m16n8k16.row.col.f16.f16.f16.f16 "
        "{%0,%1}, {%2,%3,%4,%5}, {%6,%7}, {%0,%1};"
        : "+r"(d[0]), "+r"(d[1])
        : "r"(a[0]), "r"(a[1]), "r"(a[2]), "r"(a[3]), "r"(b0), "r"(b1));
}

__device__ __forceinline__ void store2(float* p, float a, float b) {
    *(float2*)p = make_float2(a, b);
}
__device__ __forceinline__ void store2(__half* p, float a, float b) {
    *(__half2*)p = __floats2half2_rn(a, b);
}

// =====================================================================
// ALL conversions in one kernel
// =====================================================================
__global__ __launch_bounds__(256)
void conv_all(const float4* __restrict__ hs,
              const float4* __restrict__ Wq, const float4* __restrict__ Wk,
              const float4* __restrict__ Wv, const float4* __restrict__ Wo,
              __half2* __restrict__ hsh, __half2* __restrict__ qkv16,
              __half2* __restrict__ o16)
{
    const int nhs = S_LEN * HID / 4;
    const int nq  = HID * HID / 4;
    const int nkv = KV_DIM * HID / 4;
    const int total = nhs + 2 * nq + 2 * nkv;
    for (int i = blockIdx.x * blockDim.x + threadIdx.x; i < total;
         i += gridDim.x * blockDim.x) {
        const float4* src;
        __half2* dst;
        int j = i;
        if (j < nhs)               { src = hs; dst = hsh; }
        else if ((j -= nhs) < nq)  { src = Wq; dst = qkv16; }
        else if ((j -= nq) < nkv)  { src = Wk; dst = qkv16 + 2 * (size_t)nq; }
        else if ((j -= nkv) < nkv) { src = Wv; dst = qkv16 + 2 * (size_t)(nq + nkv); }
        else                       { j -= nkv; src = Wo; dst = o16; }
        float4 v = src[j];
        dst[2 * j + 0] = __floats2half2_rn(v.x, v.y);
        dst[2 * j + 1] = __floats2half2_rn(v.z, v.w);
    }
}

// =====================================================================
// fp16 GEMM (fp32 accum), C = A*B^T. CTA 128x128, 8 warps. 5 buffers,
// issue-distance 3, ONE __syncthreads per stage. Column-major raster.
// 2 CTAs/SM.
// =====================================================================
#define TILE_B   10240
#define STAGE1_B (2 * TILE_B)          // 20480
#define GEMM1_SMEM (5 * STAGE1_B)      // 102400

template <typename OT>
__global__ __launch_bounds__(256, 2)
void gemm_h1(const __half* __restrict__ A, const __half* __restrict__ B,
             OT* __restrict__ C, int M, int N, int K)
{
    extern __shared__ char sm[];
    const uint32_t smb = smem_to_u32(sm);
    const int tid  = threadIdx.x;
    const int wid  = tid >> 5;
    const int lane = tid & 31;

    const int mtiles = M >> 7;
    const int bid = blockIdx.x;
    const int m0 = (bid % mtiles) * 128;
    const int n0 = (bid / mtiles) * 128;

    const int wm = wid >> 2;
    const int wn = wid & 3;

    const __half* Abase = A + (size_t)m0 * K;
    const __half* Bbase = B + (size_t)n0 * K;

    const int c0 = tid, c1 = tid + 256;
    const int r0 = c0 >> 2, kc0 = c0 & 3;
    const int r1 = c1 >> 2, kc1 = c1 & 3;

    const int a_row   = lane & 15;
    const int a_chunk = (lane >> 4) * 16;
    const int b_rowin = ((lane >> 4) << 3) + (lane & 7);
    const int b_chunk = ((lane >> 3) & 1) * 16;

    float c[4][2][2][4];
#pragma unroll
    for (int mt = 0; mt < 4; mt++)
#pragma unroll
        for (int np = 0; np < 2; np++)
#pragma unroll
            for (int h = 0; h < 2; h++)
#pragma unroll
                for (int q = 0; q < 4; q++) c[mt][np][h][q] = 0.f;

    const int nStages = K >> 5;

    auto issue = [&](int s, int buf) {
        const int k0 = s << 5;
#pragma unroll
        for (int j = 0; j < 4; j++) {
            const int t   = j >> 1;
            const int row = (j & 1) ? r1 : r0;
            const int kc  = (j & 1) ? kc1 : kc0;
            const __half* g = ((t == 0) ? Abase : Bbase) + (size_t)row * K + k0 + kc * 8;
            cp_async16(smb + buf * STAGE1_B + t * TILE_B + row * 80 + kc * 16, g);
        }
        CP_COMMIT();
    };

    issue(0, 0); issue(1, 1); issue(2, 2);

    int bufn = 3;
    int cur5 = 0;
    for (int s = 0; s < nStages; s++) {
        if (s + 3 < nStages) {
            issue(s + 3, bufn);
            CP_WAIT(3);
        } else {
            const int rem = nStages - 1 - s;
            if (rem == 2)      CP_WAIT(2);
            else if (rem == 1) CP_WAIT(1);
            else               CP_WAIT(0);
        }
        __syncthreads();

        const uint32_t base = smb + cur5 * STAGE1_B;
#pragma unroll
        for (int ks = 0; ks < 2; ks++) {
            const int koff = ks * 32;
            uint32_t a[4][4];
#pragma unroll
            for (int mt = 0; mt < 4; mt++)
                ldsm_x4(a[mt], base + (wm * 64 + mt * 16 + a_row) * 80 + a_chunk + koff);
            uint32_t b[2][4];
#pragma unroll
            for (int np = 0; np < 2; np++)
                ldsm_x4(b[np], base + TILE_B + (wn * 32 + np * 16 + b_rowin) * 80 + b_chunk + koff);
#pragma unroll
            for (int mt = 0; mt < 4; mt++)
#pragma unroll
                for (int np = 0; np < 2; np++) {
                    mma16816h(c[mt][np][0], a[mt], b[np][0], b[np][1]);
                    mma16816h(c[mt][np][1], a[mt], b[np][2], b[np][3]);
                }
        }
        if (++bufn == 5) bufn = 0;
        if (++cur5 == 5) cur5 = 0;
    }

    const int g   = lane >> 2;
    const int tig = lane & 3;
#pragma unroll
    for (int mt = 0; mt < 4; mt++)
#pragma unroll
        for (int np = 0; np < 2; np++)
#pragma unroll
            for (int h = 0; h < 2; h++) {
                const int row = m0 + wm * 64 + mt * 16 + g;
                const int col = n0 + wn * 32 + np * 16 + h * 8 + tig * 2;
                store2(C + (size_t)row * N + col,       c[mt][np][h][0], c[mt][np][h][1]);
                store2(C + (size_t)(row + 8) * N + col, c[mt][np][h][2], c[mt][np][h][3]);
            }
}

// =====================================================================
// RoPE + L2 qk-norm — fp32 trig
// =====================================================================
#define NEG_LOG2_BASE_OVER_64 (-0.29580575893f)

__global__ __launch_bounds__(128)
void rope_norm_kernel(const __half* __restrict__ QKV,
                      __half* __restrict__ Qb, __half* __restrict__ Kb,
                      const int* __restrict__ pos_ids,
                      const float* __restrict__ q_scale,
                      const float* __restrict__ k_scale)
{
    const int s = blockIdx.x;
    const int h = blockIdx.y;
    const int d = threadIdx.x;

    const __half* base;
    __half* obase;
    const float* scale;
    if (h < NH) {
        base  = QKV + (size_t)s * QKV_W + h * HD;
        obase = Qb  + (size_t)s * HID + h * HD;
        scale = q_scale;
    } else {
        base  = QKV + (size_t)s * QKV_W + HID + (h - NH) * HD;
        obase = Kb  + (size_t)s * KV_DIM + (h - NH) * HD;
        scale = k_scale;
    }

    float x     = __half2float(base[d]);
    float other = __half2float(base[d ^ 64]);

    int pos = pos_ids[s];
    int fi = d & 63;
    float ifq = exp2f((float)fi * NEG_LOG2_BASE_OVER_64);
    float arg = (float)pos * ifq;
    float c, sn;
    __sincosf(arg, &sn, &c);

    float y = (d < 64) ? (x * c - other * sn) : (x * c + other * sn);

    float y2 = y * y;
#pragma unroll
    for (int off = 16; off; off >>= 1)
        y2 += __shfl_xor_sync(0xffffffffu, y2, off);
    __shared__ float wsum[4];
    if ((d & 31) == 0) wsum[d >> 5] = y2;
    __syncthreads();
    float tot = wsum[0] + wsum[1] + wsum[2] + wsum[3];
    float norm = sqrtf(tot);

    obase[d] = __float2half(scale[d] * y / (norm + QK_EPS));
}

// =====================================================================
// fp16 flash attention.
//  - QK with fp16 accumulators (scores bounded: |s| <= ~1.005 after
//    qk-norm; 8 chained mma add <= ~3.5e-4 logit noise -> 3e-5 on P).
//  - bounded-score softmax via cubic polynomial (no max tracking).
//  - PV with fp32 accumulators.
// 3-stage ring (Q overlaid in buf2 pre-loop), double-sync per iter,
// post-sync issue. 2 CTAs/SM.
// =====================================================================
#define FROW 272
#define FTILE (64 * FROW)
#define FSTAGE (2 * FTILE)
#define FLASH_SMEM (3 * FSTAGE)             // 104448
#define SCLN 0.08838834764831845f           // 1/sqrt(128)

__global__ __launch_bounds__(128, 2)
void flash_mma(const __half* __restrict__ Qb,
               const __half* __restrict__ Kb,
               const __half* __restrict__ QKV,
               __half* __restrict__ Ohi)
{
    extern __shared__ char sm[];
    const uint32_t ST = smem_to_u32(sm);

    const int tid = threadIdx.x;
    const int wid = tid >> 5;
    const int lane = tid & 31;
    const int qt = (gridDim.x - 1) - blockIdx.x;
    const int h  = blockIdx.y;
    const int kvh = h >> 2;

    const int nkt = qt + 1;

    const __half* Kbase = Kb + kvh * HD;
    const __half* Vbase = QKV + HID + KV_DIM + kvh * HD;

    auto issue_stage = [&](int s, int b) {
        const uint32_t base = ST + b * FSTAGE;
#pragma unroll
        for (int j = 0; j < 8; j++) {
            int c = tid + 128 * j;
            int row = c >> 4, kc = c & 15;
            uint32_t so = row * FROW + kc * 16;
            cp_async16(base + so,
                       Kbase + (size_t)(s * 64 + row) * KV_DIM + kc * 8);
            cp_async16(base + FTILE + so,
                       Vbase + (size_t)(s * 64 + row) * QKV_W + kc * 8);
        }
    };

    const uint32_t QS = ST + 2 * FSTAGE;
#pragma unroll
    for (int j = 0; j < 8; j++) {
        int c = tid + 128 * j;
        int row = c >> 4, kc = c & 15;
        cp_async16(QS + row * FROW + kc * 16,
                   Qb + (size_t)(qt * 64 + row) * HID + h * HD + kc * 8);
    }
    issue_stage(0, 0);
    CP_COMMIT();
    if (nkt > 1) {
        issue_stage(1, 1);
        CP_COMMIT();
        CP_WAIT(1);
    } else {
        CP_WAIT(0);
    }
    __syncthreads();

    uint32_t q[8][4];
    {
        uint32_t qaddr = QS + (wid * 16 + (lane & 15)) * FROW + (lane >> 4) * 16;
#pragma unroll
        for (int k = 0; k < 8; k++) ldsm_x4(q[k], qaddr + k * 32);
    }
    __syncthreads();

    float l0 = 0.f, l1 = 0.f;
    float oacc[16][4];
#pragma unroll
    for (int t = 0; t < 16; t++)
#pragma unroll
        for (int e = 0; e < 4; e++) oacc[t][e] = 0.f;

    const int qrow0 = qt * 64 + wid * 16 + (lane >> 2);
    const int qrow1 = qrow0 + 8;

    const uint32_t k_off = (((lane >> 4) << 3) + (lane & 7)) * FROW + ((lane >> 3) & 1) * 16;
    const uint32_t v_off = (((lane >> 3) & 1) * 8 + (lane & 7)) * FROW + (lane >> 4) * 16;

    int bufn = 2;
    int cur3 = 0;
    for (int it = 0; it < nkt; it++) {
        if (it + 1 < nkt) CP_WAIT(1);
        else              CP_WAIT(0);
        __syncthreads();

        const uint32_t SB = ST + cur3 * FSTAGE;

        // ---- S = Q K^T, fp16 accumulators ----
        uint32_t sh[8][2];
#pragma unroll
        for (int t = 0; t < 8; t++) { sh[t][0] = 0u; sh[t][1] = 0u; }

#pragma unroll
        for (int k = 0; k < 8; k++) {
#pragma unroll
            for (int ng = 0; ng < 4; ng++) {
                uint32_t kb[4];
                ldsm_x4(kb, SB + k_off + ng * (16 * FROW) + k * 32);
                mma16816hh(sh[2 * ng],     q[k], kb[0], kb[1]);
                mma16816hh(sh[2 * ng + 1], q[k], kb[2], kb[3]);
            }
        }

        // ---- unpack + polynomial softmax numerator ----
        const bool last = (it == nkt - 1);
        const int cb = it * 64 + (lane & 3) * 2;
        float sa[8][4];
#pragma unroll
        for (int t = 0; t < 8; t++) {
            float2 rA = __half22float2(*(__half2*)&sh[t][0]);  // row r0: c, c+1
            float2 rB = __half22float2(*(__half2*)&sh[t][1]);  // row r1: c, c+1
            sa[t][0] = rA.x; sa[t][1] = rA.y;
            sa[t][2] = rB.x; sa[t][3] = rB.y;
#pragma unroll
            for (int e = 0; e < 4; e++) {
                float y = sa[t][e] * SCLN;
                float a = fmaf(y, 0.16666667f, 0.5f);
                float b = fmaf(y, a, 1.0f);
                sa[t][e] = fmaf(y, b, 1.0f);
            }
            if (last) {
                int c = cb + t * 8;
                if (c     > qrow0) sa[t][0] = 0.f;
                if (c + 1 > qrow0) sa[t][1] = 0.f;
                if (c     > qrow1) sa[t][2] = 0.f;
                if (c + 1 > qrow1) sa[t][3] = 0.f;
            }
            l0 += sa[t][0] + sa[t][1];
            l1 += sa[t][2] + sa[t][3];
        }

        // ---- O += P V (fp32 accum) ----
        const uint32_t VB = SB + FTILE;
#pragma unroll
        for (int kg = 0; kg < 4; kg++) {
            uint32_t p[4];
#pragma unroll
            for (int hh = 0; hh < 2; hh++) {
                const int t = 2 * kg + hh;
                __half2 hab = __floats2half2_rn(sa[t][0], sa[t][1]);
                __half2 hcd = __floats2half2_rn(sa[t][2], sa[t][3]);
                p[hh]     = *(uint32_t*)&hab;
                p[2 + hh] = *(uint32_t*)&hcd;
            }
            uint32_t tswap = p[2]; p[2] = p[1]; p[1] = tswap;

            const uint32_t kgo = kg * (16 * FROW) + v_off;
#pragma unroll
            for (int dg = 0; dg < 8; dg++) {
                uint32_t v4[4];
                ldsm_x4_trans(v4, VB + kgo + dg * 32);
                mma16816h(oacc[2 * dg],     p, v4[0], v4[1]);
                mma16816h(oacc[2 * dg + 1], p, v4[2], v4[3]);
            }
        }

        __syncthreads();
        if (it + 2 < nkt) {
            issue_stage(it + 2, bufn);
            CP_COMMIT();
        }

        if (++bufn == 3) bufn = 0;
        if (++cur3 == 3) cur3 = 0;
    }

    // ---- epilogue ----
    l0 += __shfl_xor_sync(0xffffffffu, l0, 1);
    l0 += __shfl_xor_sync(0xffffffffu, l0, 2);
    l1 += __shfl_xor_sync(0xffffffffu, l1, 1);
    l1 += __shfl_xor_sync(0xffffffffu, l1, 2);
    const float i0 = 1.0f / l0;
    const float i1 = 1.0f / l1;
    const int r0 = qt * 64 + wid * 16 + (lane >> 2);
    const int r1 = r0 + 8;
#pragma unroll
    for (int t = 0; t < 16; t++) {
        int col = h * HD + t * 8 + (lane & 3) * 2;
        *(__half2*)(Ohi + (size_t)r0 * HID + col) =
            __floats2half2_rn(oacc[t][0] * i0, oacc[t][1] * i0);
        *(__half2*)(Ohi + (size_t)r1 * HID + col) =
            __floats2half2_rn(oacc[t][2] * i1, oacc[t][3] * i1);
    }
}

// =====================================================================
// launch
// =====================================================================
extern "C" void kernel_launch(void* const* d_in, const int* in_sizes, int n_in,
                              void* d_out, int out_size)
{
    const float* hs  = (const float*)d_in[0];
    const int*   pos = (const int*)  d_in[1];
    const float* Wq  = (const float*)d_in[2];
    const float* Wk  = (const float*)d_in[3];
    const float* Wv  = (const float*)d_in[4];
    const float* Wo  = (const float*)d_in[5];
    const float* qsc = (const float*)d_in[6];
    const float* ksc = (const float*)d_in[7];
    float* out = (float*)d_out;

    __half *hsh, *Wqkv16, *Wo16, *QKV, *Qh, *Kh, *aoh;
    cudaGetSymbolAddress((void**)&hsh, g_hsh);
    cudaGetSymbolAddress((void**)&Wqkv16, g_Wqkv16);
    cudaGetSymbolAddress((void**)&Wo16, g_Wo16);
    cudaGetSymbolAddress((void**)&QKV, g_QKV);
    cudaGetSymbolAddress((void**)&Qh, g_Qh);
    cudaGetSymbolAddress((void**)&Kh, g_Kh);
    cudaGetSymbolAddress((void**)&aoh, g_aoh);

    cudaFuncSetAttribute(gemm_h1<__half>, cudaFuncAttributeMaxDynamicSharedMemorySize, GEMM1_SMEM);
    cudaFuncSetAttribute(gemm_h1<float>,  cudaFuncAttributeMaxDynamicSharedMemorySize, GEMM1_SMEM);
    cudaFuncSetAttribute(flash_mma, cudaFuncAttributeMaxDynamicSharedMemorySize, FLASH_SMEM);

    conv_all<<<4096, 256>>>((const float4*)hs,
                            (const float4*)Wq, (const float4*)Wk,
                            (const float4*)Wv, (const float4*)Wo,
                            (__half2*)hsh, (__half2*)Wqkv16, (__half2*)Wo16);

    gemm_h1<__half><<<(QKV_W / 128) * (S_LEN / 128), 256, GEMM1_SMEM>>>(
        hsh, Wqkv16, QKV, S_LEN, QKV_W, HID);

    rope_norm_kernel<<<dim3(S_LEN, NH + NKV), dim3(128)>>>(QKV, Qh, Kh, pos, qsc, ksc);

    flash_mma<<<dim3(S_LEN / 64, NH), 128, FLASH_SMEM>>>(Qh, Kh, QKV, aoh);

    gemm_h1<float><<<(HID / 128) * (S_LEN / 128), 256, GEMM1_SMEM>>>(
        aoh, Wo16, out, S_LEN, HID, HID);
}

// round 15
// speedup vs baseline: 1.0124x; 1.0124x over previous
#include <cuda_runtime.h>
#include <cuda_fp16.h>
#include <math.h>
#include <stdint.h>

#define S_LEN 2048
#define HID   4096
#define NH    32
#define NKV   8
#define HD    128
#define KV_DIM 1024
#define QKV_W 6144
#define QK_EPS 1e-6f

// ---------------- scratch ----------------
__device__ __half g_hsh[S_LEN * HID];
__device__ __half g_Wqkv16[QKV_W * HID];
__device__ __half g_Wo16[HID * HID];
__device__ __half g_QKV[S_LEN * QKV_W];
__device__ __half g_Qh[S_LEN * HID];
__device__ __half g_Kh[S_LEN * KV_DIM];
__device__ __half g_aoh[S_LEN * HID];

// =====================================================================
// portable PTX helpers
// =====================================================================
__device__ __forceinline__ uint32_t smem_to_u32(const void* smem_ptr) {
    uint32_t addr;
    asm("{ .reg .u64 tmp; cvta.to.shared.u64 tmp, %1; cvt.u32.u64 %0, tmp; }"
        : "=r"(addr) : "l"(smem_ptr));
    return addr;
}

__device__ __forceinline__ void cp_async16(uint32_t dst, const void* src) {
    asm volatile("cp.async.cg.shared.global [%0], [%1], 16;"
                 :: "r"(dst), "l"(src));
}
#define CP_COMMIT() asm volatile("cp.async.commit_group;" ::: "memory")
#define CP_WAIT(n)  asm volatile("cp.async.wait_group %0;" :: "n"(n) : "memory")

__device__ __forceinline__ void ldsm_x4(uint32_t (&r)[4], uint32_t addr) {
    asm volatile("ldmatrix.sync.aligned.m8n8.x4.shared.b16 {%0,%1,%2,%3}, [%4];"
        : "=r"(r[0]), "=r"(r[1]), "=r"(r[2]), "=r"(r[3]) : "r"(addr));
}

__device__ __forceinline__ void ldsm_x4_trans(uint32_t (&r)[4], uint32_t addr) {
    asm volatile("ldmatrix.sync.aligned.m8n8.x4.trans.shared.b16 {%0,%1,%2,%3}, [%4];"
        : "=r"(r[0]), "=r"(r[1]), "=r"(r[2]), "=r"(r[3]) : "r"(addr));
}

__device__ __forceinline__ void mma16816h(float (&d)[4], const uint32_t (&a)[4],
                                          uint32_t b0, uint32_t b1) {
    asm volatile(
        "mma.sync.aligned.m16n8k16.row.col.f32.f16.f16.f32 "
        "{%0,%1,%2,%3}, {%4,%5,%6,%7}, {%8,%9}, {%0,%1,%2,%3};"
        : "+f"(d[0]), "+f"(d[1]), "+f"(d[2]), "+f"(d[3])
        : "r"(a[0]), "r"(a[1]), "r"(a[2]), "r"(a[3]), "r"(b0), "r"(b1));
}

__device__ __forceinline__ void store2(float* p, float a, float b) {
    *(float2*)p = make_float2(a, b);
}
__device__ __forceinline__ void store2(__half* p, float a, float b) {
    *(__half2*)p = __floats2half2_rn(a, b);
}

// =====================================================================
// conversions: branch-free segment loops, 32B loads / 16B stores
// =====================================================================
__device__ __forceinline__ void conv_seg(const float4* __restrict__ s,
                                         uint4* __restrict__ d, int n8,
                                         int gtid, int gsz)
{
    for (int i = gtid; i < n8; i += gsz) {
        float4 a = s[2 * i], b = s[2 * i + 1];
        __half2 h0 = __floats2half2_rn(a.x, a.y);
        __half2 h1 = __floats2half2_rn(a.z, a.w);
        __half2 h2 = __floats2half2_rn(b.x, b.y);
        __half2 h3 = __floats2half2_rn(b.z, b.w);
        uint4 o;
        o.x = *(uint32_t*)&h0; o.y = *(uint32_t*)&h1;
        o.z = *(uint32_t*)&h2; o.w = *(uint32_t*)&h3;
        d[i] = o;
    }
}

__global__ __launch_bounds__(256)
void conv_all(const float4* __restrict__ hs,
              const float4* __restrict__ Wq, const float4* __restrict__ Wk,
              const float4* __restrict__ Wv, const float4* __restrict__ Wo,
              uint4* __restrict__ hsh, uint4* __restrict__ qkv16,
              uint4* __restrict__ o16)
{
    const int gtid = blockIdx.x * blockDim.x + threadIdx.x;
    const int gsz  = gridDim.x * blockDim.x;
    const int nhs8 = S_LEN * HID / 8;
    const int nq8  = HID * HID / 8;
    const int nkv8 = KV_DIM * HID / 8;
    conv_seg(hs, hsh, nhs8, gtid, gsz);
    conv_seg(Wq, qkv16, nq8, gtid, gsz);
    conv_seg(Wk, qkv16 + nq8, nkv8, gtid, gsz);
    conv_seg(Wv, qkv16 + nq8 + nkv8, nkv8, gtid, gsz);
    conv_seg(Wo, o16, nq8, gtid, gsz);
}

// =====================================================================
// fp16 GEMM (fp32 accum), C = A*B^T. CTA 128x128, 8 warps. 5 buffers,
// issue-distance 3, ONE __syncthreads per stage. Column-major raster.
// 2 CTAs/SM.  (unchanged from R13)
// =====================================================================
#define TILE_B   10240
#define STAGE1_B (2 * TILE_B)
#define GEMM1_SMEM (5 * STAGE1_B)      // 102400

template <typename OT>
__global__ __launch_bounds__(256, 2)
void gemm_h1(const __half* __restrict__ A, const __half* __restrict__ B,
             OT* __restrict__ C, int M, int N, int K)
{
    extern __shared__ char sm[];
    const uint32_t smb = smem_to_u32(sm);
    const int tid  = threadIdx.x;
    const int wid  = tid >> 5;
    const int lane = tid & 31;

    const int mtiles = M >> 7;
    const int bid = blockIdx.x;
    const int m0 = (bid % mtiles) * 128;
    const int n0 = (bid / mtiles) * 128;

    const int wm = wid >> 2;
    const int wn = wid & 3;

    const __half* Abase = A + (size_t)m0 * K;
    const __half* Bbase = B + (size_t)n0 * K;

    const int c0 = tid, c1 = tid + 256;
    const int r0 = c0 >> 2, kc0 = c0 & 3;
    const int r1 = c1 >> 2, kc1 = c1 & 3;

    const int a_row   = lane & 15;
    const int a_chunk = (lane >> 4) * 16;
    const int b_rowin = ((lane >> 4) << 3) + (lane & 7);
    const int b_chunk = ((lane >> 3) & 1) * 16;

    float c[4][2][2][4];
#pragma unroll
    for (int mt = 0; mt < 4; mt++)
#pragma unroll
        for (int np = 0; np < 2; np++)
#pragma unroll
            for (int h = 0; h < 2; h++)
#pragma unroll
                for (int q = 0; q < 4; q++) c[mt][np][h][q] = 0.f;

    const int nStages = K >> 5;

    auto issue = [&](int s, int buf) {
        const int k0 = s << 5;
#pragma unroll
        for (int j = 0; j < 4; j++) {
            const int t   = j >> 1;
            const int row = (j & 1) ? r1 : r0;
            const int kc  = (j & 1) ? kc1 : kc0;
            const __half* g = ((t == 0) ? Abase : Bbase) + (size_t)row * K + k0 + kc * 8;
            cp_async16(smb + buf * STAGE1_B + t * TILE_B + row * 80 + kc * 16, g);
        }
        CP_COMMIT();
    };

    issue(0, 0); issue(1, 1); issue(2, 2);

    int bufn = 3;
    int cur5 = 0;
    for (int s = 0; s < nStages; s++) {
        if (s + 3 < nStages) {
            issue(s + 3, bufn);
            CP_WAIT(3);
        } else {
            const int rem = nStages - 1 - s;
            if (rem == 2)      CP_WAIT(2);
            else if (rem == 1) CP_WAIT(1);
            else               CP_WAIT(0);
        }
        __syncthreads();

        const uint32_t base = smb + cur5 * STAGE1_B;
#pragma unroll
        for (int ks = 0; ks < 2; ks++) {
            const int koff = ks * 32;
            uint32_t a[4][4];
#pragma unroll
            for (int mt = 0; mt < 4; mt++)
                ldsm_x4(a[mt], base + (wm * 64 + mt * 16 + a_row) * 80 + a_chunk + koff);
            uint32_t b[2][4];
#pragma unroll
            for (int np = 0; np < 2; np++)
                ldsm_x4(b[np], base + TILE_B + (wn * 32 + np * 16 + b_rowin) * 80 + b_chunk + koff);
#pragma unroll
            for (int mt = 0; mt < 4; mt++)
#pragma unroll
                for (int np = 0; np < 2; np++) {
                    mma16816h(c[mt][np][0], a[mt], b[np][0], b[np][1]);
                    mma16816h(c[mt][np][1], a[mt], b[np][2], b[np][3]);
                }
        }
        if (++bufn == 5) bufn = 0;
        if (++cur5 == 5) cur5 = 0;
    }

    const int g   = lane >> 2;
    const int tig = lane & 3;
#pragma unroll
    for (int mt = 0; mt < 4; mt++)
#pragma unroll
        for (int np = 0; np < 2; np++)
#pragma unroll
            for (int h = 0; h < 2; h++) {
                const int row = m0 + wm * 64 + mt * 16 + g;
                const int col = n0 + wn * 32 + np * 16 + h * 8 + tig * 2;
                store2(C + (size_t)row * N + col,       c[mt][np][h][0], c[mt][np][h][1]);
                store2(C + (size_t)(row + 8) * N + col, c[mt][np][h][2], c[mt][np][h][3]);
            }
}

// =====================================================================
// RoPE + L2 qk-norm — fp32 trig
// =====================================================================
#define NEG_LOG2_BASE_OVER_64 (-0.29580575893f)

__global__ __launch_bounds__(128)
void rope_norm_kernel(const __half* __restrict__ QKV,
                      __half* __restrict__ Qb, __half* __restrict__ Kb,
                      const int* __restrict__ pos_ids,
                      const float* __restrict__ q_scale,
                      const float* __restrict__ k_scale)
{
    const int s = blockIdx.x;
    const int h = blockIdx.y;
    const int d = threadIdx.x;

    const __half* base;
    __half* obase;
    const float* scale;
    if (h < NH) {
        base  = QKV + (size_t)s * QKV_W + h * HD;
        obase = Qb  + (size_t)s * HID + h * HD;
        scale = q_scale;
    } else {
        base  = QKV + (size_t)s * QKV_W + HID + (h - NH) * HD;
        obase = Kb  + (size_t)s * KV_DIM + (h - NH) * HD;
        scale = k_scale;
    }

    float x     = __half2float(base[d]);
    float other = __half2float(base[d ^ 64]);

    int pos = pos_ids[s];
    int fi = d & 63;
    float ifq = exp2f((float)fi * NEG_LOG2_BASE_OVER_64);
    float arg = (float)pos * ifq;
    float c, sn;
    __sincosf(arg, &sn, &c);

    float y = (d < 64) ? (x * c - other * sn) : (x * c + other * sn);

    float y2 = y * y;
#pragma unroll
    for (int off = 16; off; off >>= 1)
        y2 += __shfl_xor_sync(0xffffffffu, y2, off);
    __shared__ float wsum[4];
    if ((d & 31) == 0) wsum[d >> 5] = y2;
    __syncthreads();
    float tot = wsum[0] + wsum[1] + wsum[2] + wsum[3];
    float norm = sqrtf(tot);

    obase[d] = __float2half(scale[d] * y / (norm + QK_EPS));
}

// =====================================================================
// fp16 flash attention, bounded-score polynomial softmax, fp32 accum.
// SINGLE sync per iteration, race-free: at top of iter `it` the sync
// seals iter it-1's readers of buffer (it-1)%3 == (it+2)%3, so stage
// it+2 is issued immediately AFTER that sync (R12 issued before -> race).
// 3-stage ring, Q overlaid in buf2 pre-loop. 2 CTAs/SM.
// =====================================================================
#define FROW 272
#define FTILE (64 * FROW)
#define FSTAGE (2 * FTILE)
#define FLASH_SMEM (3 * FSTAGE)             // 104448
#define SCLN 0.08838834764831845f           // 1/sqrt(128)

__global__ __launch_bounds__(128, 2)
void flash_mma(const __half* __restrict__ Qb,
               const __half* __restrict__ Kb,
               const __half* __restrict__ QKV,
               __half* __restrict__ Ohi)
{
    extern __shared__ char sm[];
    const uint32_t ST = smem_to_u32(sm);

    const int tid = threadIdx.x;
    const int wid = tid >> 5;
    const int lane = tid & 31;
    const int qt = (gridDim.x - 1) - blockIdx.x;
    const int h  = blockIdx.y;
    const int kvh = h >> 2;

    const int nkt = qt + 1;

    const __half* Kbase = Kb + kvh * HD;
    const __half* Vbase = QKV + HID + KV_DIM + kvh * HD;

    auto issue_stage = [&](int s, int b) {
        const uint32_t base = ST + b * FSTAGE;
#pragma unroll
        for (int j = 0; j < 8; j++) {
            int c = tid + 128 * j;
            int row = c >> 4, kc = c & 15;
            uint32_t so = row * FROW + kc * 16;
            cp_async16(base + so,
                       Kbase + (size_t)(s * 64 + row) * KV_DIM + kc * 8);
            cp_async16(base + FTILE + so,
                       Vbase + (size_t)(s * 64 + row) * QKV_W + kc * 8);
        }
    };

    const uint32_t QS = ST + 2 * FSTAGE;
#pragma unroll
    for (int j = 0; j < 8; j++) {
        int c = tid + 128 * j;
        int row = c >> 4, kc = c & 15;
        cp_async16(QS + row * FROW + kc * 16,
                   Qb + (size_t)(qt * 64 + row) * HID + h * HD + kc * 8);
    }
    issue_stage(0, 0);
    CP_COMMIT();
    if (nkt > 1) {
        issue_stage(1, 1);
        CP_COMMIT();
        CP_WAIT(1);       // group 0 (Q + stage0) retired
    } else {
        CP_WAIT(0);
    }
    __syncthreads();

    uint32_t q[8][4];
    {
        uint32_t qaddr = QS + (wid * 16 + (lane & 15)) * FROW + (lane >> 4) * 16;
#pragma unroll
        for (int k = 0; k < 8; k++) ldsm_x4(q[k], qaddr + k * 32);
    }
    // Q readers sealed by the top sync of iteration 0 (before any issue
    // can overwrite buf2), so no extra barrier needed here.

    float l0 = 0.f, l1 = 0.f;
    float oacc[16][4];
#pragma unroll
    for (int t = 0; t < 16; t++)
#pragma unroll
        for (int e = 0; e < 4; e++) oacc[t][e] = 0.f;

    const int qrow0 = qt * 64 + wid * 16 + (lane >> 2);
    const int qrow1 = qrow0 + 8;

    const uint32_t k_off = (((lane >> 4) << 3) + (lane & 7)) * FROW + ((lane >> 3) & 1) * 16;
    const uint32_t v_off = (((lane >> 3) & 1) * 8 + (lane & 7)) * FROW + (lane >> 4) * 16;

    int bufn = 2;   // (it+2)%3
    int cur3 = 0;   // it%3
    for (int it = 0; it < nkt; it++) {
        // retire stage it; pending may include it+1
        if (it + 1 < nkt) CP_WAIT(1);
        else              CP_WAIT(0);
        __syncthreads();            // seals iter it-1's reads of buf (it-1)%3
        if (it + 2 < nkt) {
            issue_stage(it + 2, bufn);   // writes buf (it+2)%3 == (it-1)%3: safe
            CP_COMMIT();
        }

        const uint32_t SB = ST + cur3 * FSTAGE;

        // ---- S = Q K^T (fp32 accum) ----
        float sa[8][4];
#pragma unroll
        for (int t = 0; t < 8; t++)
#pragma unroll
            for (int e = 0; e < 4; e++) sa[t][e] = 0.f;

#pragma unroll
        for (int k = 0; k < 8; k++) {
#pragma unroll
            for (int ng = 0; ng < 4; ng++) {
                uint32_t kb[4];
                ldsm_x4(kb, SB + k_off + ng * (16 * FROW) + k * 32);
                mma16816h(sa[2 * ng],     q[k], kb[0], kb[1]);
                mma16816h(sa[2 * ng + 1], q[k], kb[2], kb[3]);
            }
        }

        // ---- polynomial softmax numerator ----
        const bool last = (it == nkt - 1);
        const int cb = it * 64 + (lane & 3) * 2;
#pragma unroll
        for (int t = 0; t < 8; t++) {
#pragma unroll
            for (int e = 0; e < 4; e++) {
                float y = sa[t][e] * SCLN;
                float a = fmaf(y, 0.16666667f, 0.5f);
                float b = fmaf(y, a, 1.0f);
                sa[t][e] = fmaf(y, b, 1.0f);
            }
            if (last) {
                int c = cb + t * 8;
                if (c     > qrow0) sa[t][0] = 0.f;
                if (c + 1 > qrow0) sa[t][1] = 0.f;
                if (c     > qrow1) sa[t][2] = 0.f;
                if (c + 1 > qrow1) sa[t][3] = 0.f;
            }
            l0 += sa[t][0] + sa[t][1];
            l1 += sa[t][2] + sa[t][3];
        }

        // ---- O += P V (fp32 accum) ----
        const uint32_t VB = SB + FTILE;
#pragma unroll
        for (int kg = 0; kg < 4; kg++) {
            uint32_t p[4];
#pragma unroll
            for (int hh = 0; hh < 2; hh++) {
                const int t = 2 * kg + hh;
                __half2 hab = __floats2half2_rn(sa[t][0], sa[t][1]);
                __half2 hcd = __floats2half2_rn(sa[t][2], sa[t][3]);
                p[hh]     = *(uint32_t*)&hab;
                p[2 + hh] = *(uint32_t*)&hcd;
            }
            uint32_t tswap = p[2]; p[2] = p[1]; p[1] = tswap;

            const uint32_t kgo = kg * (16 * FROW) + v_off;
#pragma unroll
            for (int dg = 0; dg < 8; dg++) {
                uint32_t v4[4];
                ldsm_x4_trans(v4, VB + kgo + dg * 32);
                mma16816h(oacc[2 * dg],     p, v4[0], v4[1]);
                mma16816h(oacc[2 * dg + 1], p, v4[2], v4[3]);
            }
        }

        if (++bufn == 3) bufn = 0;
        if (++cur3 == 3) cur3 = 0;
    }

    // ---- epilogue ----
    l0 += __shfl_xor_sync(0xffffffffu, l0, 1);
    l0 += __shfl_xor_sync(0xffffffffu, l0, 2);
    l1 += __shfl_xor_sync(0xffffffffu, l1, 1);
    l1 += __shfl_xor_sync(0xffffffffu, l1, 2);
    const float i0 = 1.0f / l0;
    const float i1 = 1.0f / l1;
    const int r0 = qt * 64 + wid * 16 + (lane >> 2);
    const int r1 = r0 + 8;
#pragma unroll
    for (int t = 0; t < 16; t++) {
        int col = h * HD + t * 8 + (lane & 3) * 2;
        *(__half2*)(Ohi + (size_t)r0 * HID + col) =
            __floats2half2_rn(oacc[t][0] * i0, oacc[t][1] * i0);
        *(__half2*)(Ohi + (size_t)r1 * HID + col) =
            __floats2half2_rn(oacc[t][2] * i1, oacc[t][3] * i1);
    }
}

// =====================================================================
// launch
// =====================================================================
extern "C" void kernel_launch(void* const* d_in, const int* in_sizes, int n_in,
                              void* d_out, int out_size)
{
    const float* hs  = (const float*)d_in[0];
    const int*   pos = (const int*)  d_in[1];
    const float* Wq  = (const float*)d_in[2];
    const float* Wk  = (const float*)d_in[3];
    const float* Wv  = (const float*)d_in[4];
    const float* Wo  = (const float*)d_in[5];
    const float* qsc = (const float*)d_in[6];
    const float* ksc = (const float*)d_in[7];
    float* out = (float*)d_out;

    __half *hsh, *Wqkv16, *Wo16, *QKV, *Qh, *Kh, *aoh;
    cudaGetSymbolAddress((void**)&hsh, g_hsh);
    cudaGetSymbolAddress((void**)&Wqkv16, g_Wqkv16);
    cudaGetSymbolAddress((void**)&Wo16, g_Wo16);
    cudaGetSymbolAddress((void**)&QKV, g_QKV);
    cudaGetSymbolAddress((void**)&Qh, g_Qh);
    cudaGetSymbolAddress((void**)&Kh, g_Kh);
    cudaGetSymbolAddress((void**)&aoh, g_aoh);

    cudaFuncSetAttribute(gemm_h1<__half>, cudaFuncAttributeMaxDynamicSharedMemorySize, GEMM1_SMEM);
    cudaFuncSetAttribute(gemm_h1<float>,  cudaFuncAttributeMaxDynamicSharedMemorySize, GEMM1_SMEM);
    cudaFuncSetAttribute(flash_mma, cudaFuncAttributeMaxDynamicSharedMemorySize, FLASH_SMEM);

    conv_all<<<2048, 256>>>((const float4*)hs,
                            (const float4*)Wq, (const float4*)Wk,
                            (const float4*)Wv, (const float4*)Wo,
                            (uint4*)hsh, (uint4*)Wqkv16, (uint4*)Wo16);

    gemm_h1<__half><<<(QKV_W / 128) * (S_LEN / 128), 256, GEMM1_SMEM>>>(
        hsh, Wqkv16, QKV, S_LEN, QKV_W, HID);

    rope_norm_kernel<<<dim3(S_LEN, NH + NKV), dim3(128)>>>(QKV, Qh, Kh, pos, qsc, ksc);

    flash_mma<<<dim3(S_LEN / 64, NH), 128, FLASH_SMEM>>>(Qh, Kh, QKV, aoh);

    gemm_h1<float><<<(HID / 128) * (S_LEN / 128), 256, GEMM1_SMEM>>>(
        aoh, Wo16, out, S_LEN, HID, HID);
}

// round 16
// speedup vs baseline: 1.0351x; 1.0224x over previous
#include <cuda_runtime.h>
#include <cuda_fp16.h>
#include <math.h>
#include <stdint.h>

#define S_LEN 2048
#define HID   4096
#define NH    32
#define NKV   8
#define HD    128
#define KV_DIM 1024
#define QKV_W 6144
#define QK_EPS 1e-6f

// ---------------- scratch ----------------
__device__ __half g_hsh[S_LEN * HID];
__device__ __half g_Wqkv16[QKV_W * HID];
__device__ __half g_Wo16[HID * HID];
__device__ __half g_QKV[S_LEN * QKV_W];
__device__ __half g_Qh[S_LEN * HID];
__device__ __half g_Kh[S_LEN * KV_DIM];
__device__ __half g_aoh[S_LEN * HID];

// =====================================================================
// portable PTX helpers
// =====================================================================
__device__ __forceinline__ uint32_t smem_to_u32(const void* smem_ptr) {
    uint32_t addr;
    asm("{ .reg .u64 tmp; cvta.to.shared.u64 tmp, %1; cvt.u32.u64 %0, tmp; }"
        : "=r"(addr) : "l"(smem_ptr));
    return addr;
}

__device__ __forceinline__ void cp_async16(uint32_t dst, const void* src) {
    asm volatile("cp.async.cg.shared.global [%0], [%1], 16;"
                 :: "r"(dst), "l"(src));
}
#define CP_COMMIT() asm volatile("cp.async.commit_group;" ::: "memory")
#define CP_WAIT(n)  asm volatile("cp.async.wait_group %0;" :: "n"(n) : "memory")

__device__ __forceinline__ void ldsm_x4(uint32_t (&r)[4], uint32_t addr) {
    asm volatile("ldmatrix.sync.aligned.m8n8.x4.shared.b16 {%0,%1,%2,%3}, [%4];"
        : "=r"(r[0]), "=r"(r[1]), "=r"(r[2]), "=r"(r[3]) : "r"(addr));
}

__device__ __forceinline__ void ldsm_x4_trans(uint32_t (&r)[4], uint32_t addr) {
    asm volatile("ldmatrix.sync.aligned.m8n8.x4.trans.shared.b16 {%0,%1,%2,%3}, [%4];"
        : "=r"(r[0]), "=r"(r[1]), "=r"(r[2]), "=r"(r[3]) : "r"(addr));
}

__device__ __forceinline__ void mma16816h(float (&d)[4], const uint32_t (&a)[4],
                                          uint32_t b0, uint32_t b1) {
    asm volatile(
        "mma.sync.aligned.m16n8k16.row.col.f32.f16.f16.f32 "
        "{%0,%1,%2,%3}, {%4,%5,%6,%7}, {%8,%9}, {%0,%1,%2,%3};"
        : "+f"(d[0]), "+f"(d[1]), "+f"(d[2]), "+f"(d[3])
        : "r"(a[0]), "r"(a[1]), "r"(a[2]), "r"(a[3]), "r"(b0), "r"(b1));
}

__device__ __forceinline__ void store2(float* p, float a, float b) {
    *(float2*)p = make_float2(a, b);
}
__device__ __forceinline__ void store2(__half* p, float a, float b) {
    *(__half2*)p = __floats2half2_rn(a, b);
}

// =====================================================================
// conversions: branch-free segment loops, 32B loads / 16B stores
// =====================================================================
__device__ __forceinline__ void conv_seg(const float4* __restrict__ s,
                                         uint4* __restrict__ d, int n8,
                                         int gtid, int gsz)
{
    for (int i = gtid; i < n8; i += gsz) {
        float4 a = s[2 * i], b = s[2 * i + 1];
        __half2 h0 = __floats2half2_rn(a.x, a.y);
        __half2 h1 = __floats2half2_rn(a.z, a.w);
        __half2 h2 = __floats2half2_rn(b.x, b.y);
        __half2 h3 = __floats2half2_rn(b.z, b.w);
        uint4 o;
        o.x = *(uint32_t*)&h0; o.y = *(uint32_t*)&h1;
        o.z = *(uint32_t*)&h2; o.w = *(uint32_t*)&h3;
        d[i] = o;
    }
}

__global__ __launch_bounds__(256)
void conv_all(const float4* __restrict__ hs,
              const float4* __restrict__ Wq, const float4* __restrict__ Wk,
              const float4* __restrict__ Wv, const float4* __restrict__ Wo,
              uint4* __restrict__ hsh, uint4* __restrict__ qkv16,
              uint4* __restrict__ o16)
{
    const int gtid = blockIdx.x * blockDim.x + threadIdx.x;
    const int gsz  = gridDim.x * blockDim.x;
    const int nhs8 = S_LEN * HID / 8;
    const int nq8  = HID * HID / 8;
    const int nkv8 = KV_DIM * HID / 8;
    conv_seg(hs, hsh, nhs8, gtid, gsz);
    conv_seg(Wq, qkv16, nq8, gtid, gsz);
    conv_seg(Wk, qkv16 + nq8, nkv8, gtid, gsz);
    conv_seg(Wv, qkv16 + nq8 + nkv8, nkv8, gtid, gsz);
    conv_seg(Wo, o16, nq8, gtid, gsz);
}

// =====================================================================
// fp16 GEMM (fp32 accum), C = A*B^T. CTA 128x128, 8 warps.
// K=64 per stage (128 rows x 128B data, 144B stride), 3-stage ring,
// post-sync issue at distance 2 (race-free), ONE sync per stage.
// Column-major raster. 2 CTAs/SM (2 x 110.6KB = 221KB <= 228KB).
// =====================================================================
#define GTILE_B  18432                 // 128 * 144
#define GSTAGE_B (2 * GTILE_B)         // 36864
#define GEMM1_SMEM (3 * GSTAGE_B)      // 110592

template <typename OT>
__global__ __launch_bounds__(256, 2)
void gemm_h1(const __half* __restrict__ A, const __half* __restrict__ B,
             OT* __restrict__ C, int M, int N, int K)
{
    extern __shared__ char sm[];
    const uint32_t smb = smem_to_u32(sm);
    const int tid  = threadIdx.x;
    const int wid  = tid >> 5;
    const int lane = tid & 31;

    const int mtiles = M >> 7;
    const int bid = blockIdx.x;
    const int m0 = (bid % mtiles) * 128;
    const int n0 = (bid / mtiles) * 128;

    const int wm = wid >> 2;
    const int wn = wid & 3;

    const __half* Abase = A + (size_t)m0 * K;
    const __half* Bbase = B + (size_t)n0 * K;

    const int a_row   = lane & 15;
    const int a_chunk = (lane >> 4) * 16;
    const int b_rowin = ((lane >> 4) << 3) + (lane & 7);
    const int b_chunk = ((lane >> 3) & 1) * 16;

    float c[4][2][2][4];
#pragma unroll
    for (int mt = 0; mt < 4; mt++)
#pragma unroll
        for (int np = 0; np < 2; np++)
#pragma unroll
            for (int h = 0; h < 2; h++)
#pragma unroll
                for (int q = 0; q < 4; q++) c[mt][np][h][q] = 0.f;

    const int nStages = K >> 6;   // K=64 per stage

    // 2048 16B-chunks per stage (2 tiles x 128 rows x 8 chunks), 8/thread
    auto issue = [&](int s, int buf) {
        const int k0 = s << 6;
#pragma unroll
        for (int j = 0; j < 8; j++) {
            const int cch = tid + 256 * j;
            const int t   = cch >> 10;          // 0 = A, 1 = B
            const int cit = cch & 1023;
            const int row = cit >> 3;
            const int kc  = cit & 7;
            const __half* g = ((t == 0) ? Abase : Bbase) + (size_t)row * K + k0 + kc * 8;
            cp_async16(smb + buf * GSTAGE_B + t * GTILE_B + row * 144 + kc * 16, g);
        }
        CP_COMMIT();
    };

    issue(0, 0); issue(1, 1);

    int bufn = 2;   // (s+2)%3
    int cur3 = 0;   // s%3
    for (int s = 0; s < nStages; s++) {
        if (s + 1 < nStages) CP_WAIT(1);
        else                 CP_WAIT(0);
        __syncthreads();              // seals iter s-1's reads of buf (s-1)%3
        if (s + 2 < nStages) {
            issue(s + 2, bufn);       // writes buf (s+2)%3 == (s-1)%3: safe
        }

        const uint32_t base = smb + cur3 * GSTAGE_B;
#pragma unroll
        for (int ks = 0; ks < 4; ks++) {
            const int koff = ks * 32;
            uint32_t a[4][4];
#pragma unroll
            for (int mt = 0; mt < 4; mt++)
                ldsm_x4(a[mt], base + (wm * 64 + mt * 16 + a_row) * 144 + a_chunk + koff);
            uint32_t b[2][4];
#pragma unroll
            for (int np = 0; np < 2; np++)
                ldsm_x4(b[np], base + GTILE_B + (wn * 32 + np * 16 + b_rowin) * 144 + b_chunk + koff);
#pragma unroll
            for (int mt = 0; mt < 4; mt++)
#pragma unroll
                for (int np = 0; np < 2; np++) {
                    mma16816h(c[mt][np][0], a[mt], b[np][0], b[np][1]);
                    mma16816h(c[mt][np][1], a[mt], b[np][2], b[np][3]);
                }
        }
        if (++bufn == 3) bufn = 0;
        if (++cur3 == 3) cur3 = 0;
    }

    const int g   = lane >> 2;
    const int tig = lane & 3;
#pragma unroll
    for (int mt = 0; mt < 4; mt++)
#pragma unroll
        for (int np = 0; np < 2; np++)
#pragma unroll
            for (int h = 0; h < 2; h++) {
                const int row = m0 + wm * 64 + mt * 16 + g;
                const int col = n0 + wn * 32 + np * 16 + h * 8 + tig * 2;
                store2(C + (size_t)row * N + col,       c[mt][np][h][0], c[mt][np][h][1]);
                store2(C + (size_t)(row + 8) * N + col, c[mt][np][h][2], c[mt][np][h][3]);
            }
}

// =====================================================================
// RoPE + L2 qk-norm — fp32 trig
// =====================================================================
#define NEG_LOG2_BASE_OVER_64 (-0.29580575893f)

__global__ __launch_bounds__(128)
void rope_norm_kernel(const __half* __restrict__ QKV,
                      __half* __restrict__ Qb, __half* __restrict__ Kb,
                      const int* __restrict__ pos_ids,
                      const float* __restrict__ q_scale,
                      const float* __restrict__ k_scale)
{
    const int s = blockIdx.x;
    const int h = blockIdx.y;
    const int d = threadIdx.x;

    const __half* base;
    __half* obase;
    const float* scale;
    if (h < NH) {
        base  = QKV + (size_t)s * QKV_W + h * HD;
        obase = Qb  + (size_t)s * HID + h * HD;
        scale = q_scale;
    } else {
        base  = QKV + (size_t)s * QKV_W + HID + (h - NH) * HD;
        obase = Kb  + (size_t)s * KV_DIM + (h - NH) * HD;
        scale = k_scale;
    }

    float x     = __half2float(base[d]);
    float other = __half2float(base[d ^ 64]);

    int pos = pos_ids[s];
    int fi = d & 63;
    float ifq = exp2f((float)fi * NEG_LOG2_BASE_OVER_64);
    float arg = (float)pos * ifq;
    float c, sn;
    __sincosf(arg, &sn, &c);

    float y = (d < 64) ? (x * c - other * sn) : (x * c + other * sn);

    float y2 = y * y;
#pragma unroll
    for (int off = 16; off; off >>= 1)
        y2 += __shfl_xor_sync(0xffffffffu, y2, off);
    __shared__ float wsum[4];
    if ((d & 31) == 0) wsum[d >> 5] = y2;
    __syncthreads();
    float tot = wsum[0] + wsum[1] + wsum[2] + wsum[3];
    float norm = sqrtf(tot);

    obase[d] = __float2half(scale[d] * y / (norm + QK_EPS));
}

// =====================================================================
// fp16 flash attention (unchanged from R15 — passing config).
// =====================================================================
#define FROW 272
#define FTILE (64 * FROW)
#define FSTAGE (2 * FTILE)
#define FLASH_SMEM (3 * FSTAGE)             // 104448
#define SCLN 0.08838834764831845f           // 1/sqrt(128)

__global__ __launch_bounds__(128, 2)
void flash_mma(const __half* __restrict__ Qb,
               const __half* __restrict__ Kb,
               const __half* __restrict__ QKV,
               __half* __restrict__ Ohi)
{
    extern __shared__ char sm[];
    const uint32_t ST = smem_to_u32(sm);

    const int tid = threadIdx.x;
    const int wid = tid >> 5;
    const int lane = tid & 31;
    const int qt = (gridDim.x - 1) - blockIdx.x;
    const int h  = blockIdx.y;
    const int kvh = h >> 2;

    const int nkt = qt + 1;

    const __half* Kbase = Kb + kvh * HD;
    const __half* Vbase = QKV + HID + KV_DIM + kvh * HD;

    auto issue_stage = [&](int s, int b) {
        const uint32_t base = ST + b * FSTAGE;
#pragma unroll
        for (int j = 0; j < 8; j++) {
            int c = tid + 128 * j;
            int row = c >> 4, kc = c & 15;
            uint32_t so = row * FROW + kc * 16;
            cp_async16(base + so,
                       Kbase + (size_t)(s * 64 + row) * KV_DIM + kc * 8);
            cp_async16(base + FTILE + so,
                       Vbase + (size_t)(s * 64 + row) * QKV_W + kc * 8);
        }
    };

    const uint32_t QS = ST + 2 * FSTAGE;
#pragma unroll
    for (int j = 0; j < 8; j++) {
        int c = tid + 128 * j;
        int row = c >> 4, kc = c & 15;
        cp_async16(QS + row * FROW + kc * 16,
                   Qb + (size_t)(qt * 64 + row) * HID + h * HD + kc * 8);
    }
    issue_stage(0, 0);
    CP_COMMIT();
    if (nkt > 1) {
        issue_stage(1, 1);
        CP_COMMIT();
        CP_WAIT(1);
    } else {
        CP_WAIT(0);
    }
    __syncthreads();

    uint32_t q[8][4];
    {
        uint32_t qaddr = QS + (wid * 16 + (lane & 15)) * FROW + (lane >> 4) * 16;
#pragma unroll
        for (int k = 0; k < 8; k++) ldsm_x4(q[k], qaddr + k * 32);
    }

    float l0 = 0.f, l1 = 0.f;
    float oacc[16][4];
#pragma unroll
    for (int t = 0; t < 16; t++)
#pragma unroll
        for (int e = 0; e < 4; e++) oacc[t][e] = 0.f;

    const int qrow0 = qt * 64 + wid * 16 + (lane >> 2);
    const int qrow1 = qrow0 + 8;

    const uint32_t k_off = (((lane >> 4) << 3) + (lane & 7)) * FROW + ((lane >> 3) & 1) * 16;
    const uint32_t v_off = (((lane >> 3) & 1) * 8 + (lane & 7)) * FROW + (lane >> 4) * 16;

    int bufn = 2;
    int cur3 = 0;
    for (int it = 0; it < nkt; it++) {
        if (it + 1 < nkt) CP_WAIT(1);
        else              CP_WAIT(0);
        __syncthreads();
        if (it + 2 < nkt) {
            issue_stage(it + 2, bufn);
            CP_COMMIT();
        }

        const uint32_t SB = ST + cur3 * FSTAGE;

        float sa[8][4];
#pragma unroll
        for (int t = 0; t < 8; t++)
#pragma unroll
            for (int e = 0; e < 4; e++) sa[t][e] = 0.f;

#pragma unroll
        for (int k = 0; k < 8; k++) {
#pragma unroll
            for (int ng = 0; ng < 4; ng++) {
                uint32_t kb[4];
                ldsm_x4(kb, SB + k_off + ng * (16 * FROW) + k * 32);
                mma16816h(sa[2 * ng],     q[k], kb[0], kb[1]);
                mma16816h(sa[2 * ng + 1], q[k], kb[2], kb[3]);
            }
        }

        const bool last = (it == nkt - 1);
        const int cb = it * 64 + (lane & 3) * 2;
#pragma unroll
        for (int t = 0; t < 8; t++) {
#pragma unroll
            for (int e = 0; e < 4; e++) {
                float y = sa[t][e] * SCLN;
                float a = fmaf(y, 0.16666667f, 0.5f);
                float b = fmaf(y, a, 1.0f);
                sa[t][e] = fmaf(y, b, 1.0f);
            }
            if (last) {
                int c = cb + t * 8;
                if (c     > qrow0) sa[t][0] = 0.f;
                if (c + 1 > qrow0) sa[t][1] = 0.f;
                if (c     > qrow1) sa[t][2] = 0.f;
                if (c + 1 > qrow1) sa[t][3] = 0.f;
            }
            l0 += sa[t][0] + sa[t][1];
            l1 += sa[t][2] + sa[t][3];
        }

        const uint32_t VB = SB + FTILE;
#pragma unroll
        for (int kg = 0; kg < 4; kg++) {
            uint32_t p[4];
#pragma unroll
            for (int hh = 0; hh < 2; hh++) {
                const int t = 2 * kg + hh;
                __half2 hab = __floats2half2_rn(sa[t][0], sa[t][1]);
                __half2 hcd = __floats2half2_rn(sa[t][2], sa[t][3]);
                p[hh]     = *(uint32_t*)&hab;
                p[2 + hh] = *(uint32_t*)&hcd;
            }
            uint32_t tswap = p[2]; p[2] = p[1]; p[1] = tswap;

            const uint32_t kgo = kg * (16 * FROW) + v_off;
#pragma unroll
            for (int dg = 0; dg < 8; dg++) {
                uint32_t v4[4];
                ldsm_x4_trans(v4, VB + kgo + dg * 32);
                mma16816h(oacc[2 * dg],     p, v4[0], v4[1]);
                mma16816h(oacc[2 * dg + 1], p, v4[2], v4[3]);
            }
        }

        if (++bufn == 3) bufn = 0;
        if (++cur3 == 3) cur3 = 0;
    }

    l0 += __shfl_xor_sync(0xffffffffu, l0, 1);
    l0 += __shfl_xor_sync(0xffffffffu, l0, 2);
    l1 += __shfl_xor_sync(0xffffffffu, l1, 1);
    l1 += __shfl_xor_sync(0xffffffffu, l1, 2);
    const float i0 = 1.0f / l0;
    const float i1 = 1.0f / l1;
    const int r0 = qt * 64 + wid * 16 + (lane >> 2);
    const int r1 = r0 + 8;
#pragma unroll
    for (int t = 0; t < 16; t++) {
        int col = h * HD + t * 8 + (lane & 3) * 2;
        *(__half2*)(Ohi + (size_t)r0 * HID + col) =
            __floats2half2_rn(oacc[t][0] * i0, oacc[t][1] * i0);
        *(__half2*)(Ohi + (size_t)r1 * HID + col) =
            __floats2half2_rn(oacc[t][2] * i1, oacc[t][3] * i1);
    }
}

// =====================================================================
// launch
// =====================================================================
extern "C" void kernel_launch(void* const* d_in, const int* in_sizes, int n_in,
                              void* d_out, int out_size)
{
    const float* hs  = (const float*)d_in[0];
    const int*   pos = (const int*)  d_in[1];
    const float* Wq  = (const float*)d_in[2];
    const float* Wk  = (const float*)d_in[3];
    const float* Wv  = (const float*)d_in[4];
    const float* Wo  = (const float*)d_in[5];
    const float* qsc = (const float*)d_in[6];
    const float* ksc = (const float*)d_in[7];
    float* out = (float*)d_out;

    __half *hsh, *Wqkv16, *Wo16, *QKV, *Qh, *Kh, *aoh;
    cudaGetSymbolAddress((void**)&hsh, g_hsh);
    cudaGetSymbolAddress((void**)&Wqkv16, g_Wqkv16);
    cudaGetSymbolAddress((void**)&Wo16, g_Wo16);
    cudaGetSymbolAddress((void**)&QKV, g_QKV);
    cudaGetSymbolAddress((void**)&Qh, g_Qh);
    cudaGetSymbolAddress((void**)&Kh, g_Kh);
    cudaGetSymbolAddress((void**)&aoh, g_aoh);

    cudaFuncSetAttribute(gemm_h1<__half>, cudaFuncAttributeMaxDynamicSharedMemorySize, GEMM1_SMEM);
    cudaFuncSetAttribute(gemm_h1<float>,  cudaFuncAttributeMaxDynamicSharedMemorySize, GEMM1_SMEM);
    cudaFuncSetAttribute(flash_mma, cudaFuncAttributeMaxDynamicSharedMemorySize, FLASH_SMEM);

    conv_all<<<2048, 256>>>((const float4*)hs,
                            (const float4*)Wq, (const float4*)Wk,
                            (const float4*)Wv, (const float4*)Wo,
                            (uint4*)hsh, (uint4*)Wqkv16, (uint4*)Wo16);

    gemm_h1<__half><<<(QKV_W / 128) * (S_LEN / 128), 256, GEMM1_SMEM>>>(
        hsh, Wqkv16, QKV, S_LEN, QKV_W, HID);

    rope_norm_kernel<<<dim3(S_LEN, NH + NKV), dim3(128)>>>(QKV, Qh, Kh, pos, qsc, ksc);

    flash_mma<<<dim3(S_LEN / 64, NH), 128, FLASH_SMEM>>>(Qh, Kh, QKV, aoh);

    gemm_h1<float><<<(HID / 128) * (S_LEN / 128), 256, GEMM1_SMEM>>>(
        aoh, Wo16, out, S_LEN, HID, HID);
}